// round 12
// baseline (speedup 1.0000x reference)
#include <cuda_runtime.h>
#include <math.h>

// Problem dims
#define PP   8192      // N*H*W
#define DD   256
#define SS   16
#define HH   64
#define WW   64
#define MLPH 1024

// ---------------- scratch (device globals; no runtime allocation) ----------
__device__ float g_off [PP * 32];        // [P, S, 2] scaled offsets
__device__ float g_ek  [PP * DD];        // e @ Wk
__device__ float g_ev  [PP * DD];        // e @ Wv
__device__ float g_q   [PP * DD];        // hs @ Wq + bq
__device__ float g_attn[PP * DD];        // attention output (pre-Wo)
__device__ float g_x   [PP * DD];        // after LN1
__device__ float g_h   [PP * MLPH];     // gelu(x@W1+b1)
__device__ float g_Wck [2 * DD];         // W_kvp @ Wk
__device__ float g_Wcv [2 * DD];         // W_kvp @ Wv
__device__ float g_bck [DD];             // b_kvp @ Wk + bk
__device__ float g_bcv [DD];             // b_kvp @ Wv + bv

// ---------------- small helpers --------------------------------------------
__device__ __forceinline__ float gelu_f(float x) {
    // JAX gelu approximate=True (tanh form)
    float x3 = x * x * x;
    return 0.5f * x * (1.0f + tanhf(0.7978845608028654f * (x + 0.044715f * x3)));
}

// ---------------- K0: fold W_kvp/b_kvp through Wk/Wv ------------------------
__global__ void precompute_kernel(const float* __restrict__ W_kvp,
                                  const float* __restrict__ b_kvp,
                                  const float* __restrict__ Wk,
                                  const float* __restrict__ bk,
                                  const float* __restrict__ Wv,
                                  const float* __restrict__ bv) {
    int e = threadIdx.x;  // 0..255 output column (a*64+hd)
    float wk0 = 0.f, wk1 = 0.f, wv0 = 0.f, wv1 = 0.f, bkk = 0.f, bvv = 0.f;
    for (int d = 0; d < DD; d++) {
        float wkd = Wk[d * DD + e];
        float wvd = Wv[d * DD + e];
        float k0w = W_kvp[d];         // W_kvp[0][d]
        float k1w = W_kvp[DD + d];    // W_kvp[1][d]
        float bkv = b_kvp[d];
        wk0 += k0w * wkd; wk1 += k1w * wkd;
        wv0 += k0w * wvd; wv1 += k1w * wvd;
        bkk += bkv * wkd; bvv += bkv * wvd;
    }
    g_Wck[e] = wk0; g_Wck[DD + e] = wk1;
    g_Wcv[e] = wv0; g_Wcv[DD + e] = wv1;
    g_bck[e] = bkk + bk[e];
    g_bcv[e] = bvv + bv[e];
}

// ---------------- K1: offset predictor --------------------------------------
__global__ void off_kernel(const float* __restrict__ hs,
                           const float* __restrict__ W_off,
                           const float* __restrict__ b_off) {
    int p = blockIdx.x;
    int t = threadIdx.x;            // 256 threads
    __shared__ float s_hs[DD];
    __shared__ float s_part[8][32];
    s_hs[t] = hs[p * DD + t];
    __syncthreads();
    int o = t & 31;                 // output index s*2+k, 0..31
    int g = t >> 5;                 // 8 d-groups of 32
    float acc = 0.f;
#pragma unroll
    for (int j = 0; j < 32; j++) {
        int d = g * 32 + j;
        acc += s_hs[d] * W_off[d * 32 + o];   // coalesced: lanes -> consecutive o
    }
    s_part[g][o] = acc;
    __syncthreads();
    if (t < 32) {
        float s = 0.f;
#pragma unroll
        for (int gg = 0; gg < 8; gg++) s += s_part[gg][t];
        s += b_off[t];
        float sig = 1.0f / (1.0f + expf(-s));
        g_off[p * 32 + t] = 60.0f * sig - 30.0f;   // 2*30*sigmoid - 30
    }
}

// ---------------- fp32 128x128x16 double-buffered GEMM body ------------------
// C[bm:bm+128, bn:bn+128] = A[M,K] @ B[K,N] (+bias[N]) (+gelu)
template <int EPI>  // 0: bias-only, 1: bias+gelu
__device__ __forceinline__ void gemm_body(
        const float* __restrict__ A, const float* __restrict__ B,
        const float* __restrict__ bias,
        float* __restrict__ C, int N, int K, int bm, int bn) {
    __shared__ float As[2][16][128];
    __shared__ float Bs[2][16][128];
    int t = threadIdx.x;

    int a_row = t >> 1;            // 0..127
    int a_k   = (t & 1) * 8;       // 0 or 8
    int b_k   = t >> 5;            // 0..7
    int b_col = (t & 31) * 4;      // 0..124

    const float* Ap = A + (size_t)(bm + a_row) * K + a_k;
    const float* Bp = B + (size_t)b_k * N + bn + b_col;
    size_t bstride8 = (size_t)8 * N;

    int tm = (t >> 4) * 8;
    int tn = (t & 15) * 8;

    float acc[8][8] = {};

    {
        float4 av0 = *(const float4*)(Ap);
        float4 av1 = *(const float4*)(Ap + 4);
        float4 bv0 = *(const float4*)(Bp);
        float4 bv1 = *(const float4*)(Bp + bstride8);
        As[0][a_k + 0][a_row] = av0.x; As[0][a_k + 1][a_row] = av0.y;
        As[0][a_k + 2][a_row] = av0.z; As[0][a_k + 3][a_row] = av0.w;
        As[0][a_k + 4][a_row] = av1.x; As[0][a_k + 5][a_row] = av1.y;
        As[0][a_k + 6][a_row] = av1.z; As[0][a_k + 7][a_row] = av1.w;
        *(float4*)&Bs[0][b_k][b_col]     = bv0;
        *(float4*)&Bs[0][b_k + 8][b_col] = bv1;
    }
    __syncthreads();

    int nk = K / 16;
    for (int ki = 0; ki < nk; ki++) {
        int cur = ki & 1;
        float4 av0, av1, bv0, bv1;
        if (ki + 1 < nk) {
            int k0 = (ki + 1) * 16;
            av0 = *(const float4*)(Ap + k0);
            av1 = *(const float4*)(Ap + k0 + 4);
            bv0 = *(const float4*)(Bp + (size_t)k0 * N);
            bv1 = *(const float4*)(Bp + (size_t)k0 * N + bstride8);
        }
#pragma unroll
        for (int kk = 0; kk < 16; kk++) {
            float4 a40 = *(const float4*)&As[cur][kk][tm];
            float4 a41 = *(const float4*)&As[cur][kk][tm + 4];
            float4 b40 = *(const float4*)&Bs[cur][kk][tn];
            float4 b41 = *(const float4*)&Bs[cur][kk][tn + 4];
            float ar[8] = {a40.x, a40.y, a40.z, a40.w, a41.x, a41.y, a41.z, a41.w};
            float br[8] = {b40.x, b40.y, b40.z, b40.w, b41.x, b41.y, b41.z, b41.w};
#pragma unroll
            for (int i = 0; i < 8; i++)
#pragma unroll
                for (int j = 0; j < 8; j++)
                    acc[i][j] += ar[i] * br[j];
        }
        if (ki + 1 < nk) {
            int nxt = cur ^ 1;
            As[nxt][a_k + 0][a_row] = av0.x; As[nxt][a_k + 1][a_row] = av0.y;
            As[nxt][a_k + 2][a_row] = av0.z; As[nxt][a_k + 3][a_row] = av0.w;
            As[nxt][a_k + 4][a_row] = av1.x; As[nxt][a_k + 5][a_row] = av1.y;
            As[nxt][a_k + 6][a_row] = av1.z; As[nxt][a_k + 7][a_row] = av1.w;
            *(float4*)&Bs[nxt][b_k][b_col]     = bv0;
            *(float4*)&Bs[nxt][b_k + 8][b_col] = bv1;
            __syncthreads();
        }
    }

    float bcol[8];
#pragma unroll
    for (int j = 0; j < 8; j++) bcol[j] = bias ? __ldg(&bias[bn + tn + j]) : 0.f;
#pragma unroll
    for (int i = 0; i < 8; i++) {
        int row = bm + tm + i;
        float v[8];
#pragma unroll
        for (int j = 0; j < 8; j++) {
            v[j] = acc[i][j] + bcol[j];
            if (EPI == 1) v[j] = gelu_f(v[j]);
        }
        *(float4*)(C + (size_t)row * N + bn + tn)     = make_float4(v[0], v[1], v[2], v[3]);
        *(float4*)(C + (size_t)row * N + bn + tn + 4) = make_float4(v[4], v[5], v[6], v[7]);
    }
}

template <int EPI>
__global__ void __launch_bounds__(256)
gemm_kernel(const float* __restrict__ A, const float* __restrict__ B,
            const float* __restrict__ bias,
            float* __restrict__ C, int N, int K) {
    gemm_body<EPI>(A, B, bias, C, N, K, blockIdx.y * 128, blockIdx.x * 128);
}

// Batched K/V/Q projections in one launch (blockIdx.z selects the GEMM)
__global__ void __launch_bounds__(256)
qkv_kernel(const float* __restrict__ ehs, const float* __restrict__ hs,
           const float* __restrict__ Wk, const float* __restrict__ Wv,
           const float* __restrict__ Wq, const float* __restrict__ bq,
           float* __restrict__ ek, float* __restrict__ ev, float* __restrict__ q) {
    int bm = blockIdx.y * 128, bn = blockIdx.x * 128;
    if (blockIdx.z == 0)
        gemm_body<0>(ehs, Wk, nullptr, ek, DD, DD, bm, bn);
    else if (blockIdx.z == 1)
        gemm_body<0>(ehs, Wv, nullptr, ev, DD, DD, bm, bn);
    else
        gemm_body<0>(hs, Wq, bq, q, DD, DD, bm, bn);
}

// ---------- fused GEMM(64x256 tile) + bias + residual + LayerNorm ------------
// C[row] = LN( A[row]@B + bias + R[row] ) * lns + lnb,   N fixed = 256.
// 256 threads: warp w owns rows bm+w*8..+7 entirely (lane l holds cols l*8..l*8+7),
// so row mean/var is a warp shuffle reduction.
__global__ void __launch_bounds__(256)
ln_gemm_kernel(const float* __restrict__ A, const float* __restrict__ B,
               const float* __restrict__ bias, const float* __restrict__ R,
               const float* __restrict__ lns, const float* __restrict__ lnb,
               float* __restrict__ C, int K) {
    __shared__ float As[2][16][64];
    __shared__ float Bs[2][16][256];
    int t  = threadIdx.x;
    int bm = blockIdx.x * 64;

    // A-load: thread t loads one float4: row = t>>2 (0..63), k = (t&3)*4
    int a_row = t >> 2;
    int a_k   = (t & 3) * 4;
    // B-load: thread t loads 4 float4s: k row = t>>4 (0..15), cols (t&15)*4 + j*64
    int b_k = t >> 4;
    int b_c = (t & 15) * 4;

    const float* Ap = A + (size_t)(bm + a_row) * K + a_k;
    const float* Bp = B + (size_t)b_k * 256 + b_c;

    int tm = (t >> 5) * 8;         // warp -> 8 rows
    int tn = (t & 31) * 8;         // lane -> 8 cols (covers all 256)

    float acc[8][8] = {};

    // prologue
    {
        float4 av = *(const float4*)Ap;
        As[0][a_k + 0][a_row] = av.x; As[0][a_k + 1][a_row] = av.y;
        As[0][a_k + 2][a_row] = av.z; As[0][a_k + 3][a_row] = av.w;
#pragma unroll
        for (int j = 0; j < 4; j++)
            *(float4*)&Bs[0][b_k][b_c + j * 64] = *(const float4*)(Bp + j * 64);
    }
    __syncthreads();

    int nk = K / 16;
    for (int ki = 0; ki < nk; ki++) {
        int cur = ki & 1;
        float4 av;
        float4 bv[4];
        if (ki + 1 < nk) {
            int k0 = (ki + 1) * 16;
            av = *(const float4*)(Ap + k0);
#pragma unroll
            for (int j = 0; j < 4; j++)
                bv[j] = *(const float4*)(Bp + (size_t)k0 * 256 + j * 64);
        }
#pragma unroll
        for (int kk = 0; kk < 16; kk++) {
            float4 a40 = *(const float4*)&As[cur][kk][tm];
            float4 a41 = *(const float4*)&As[cur][kk][tm + 4];
            float4 b40 = *(const float4*)&Bs[cur][kk][tn];
            float4 b41 = *(const float4*)&Bs[cur][kk][tn + 4];
            float ar[8] = {a40.x, a40.y, a40.z, a40.w, a41.x, a41.y, a41.z, a41.w};
            float br[8] = {b40.x, b40.y, b40.z, b40.w, b41.x, b41.y, b41.z, b41.w};
#pragma unroll
            for (int i = 0; i < 8; i++)
#pragma unroll
                for (int j = 0; j < 8; j++)
                    acc[i][j] += ar[i] * br[j];
        }
        if (ki + 1 < nk) {
            int nxt = cur ^ 1;
            As[nxt][a_k + 0][a_row] = av.x; As[nxt][a_k + 1][a_row] = av.y;
            As[nxt][a_k + 2][a_row] = av.z; As[nxt][a_k + 3][a_row] = av.w;
#pragma unroll
            for (int j = 0; j < 4; j++)
                *(float4*)&Bs[nxt][b_k][b_c + j * 64] = bv[j];
            __syncthreads();
        }
    }

    // epilogue: bias + residual, then per-row LN via warp reduction
    float bcol[8], lnsv[8], lnbv[8];
#pragma unroll
    for (int j = 0; j < 8; j++) {
        bcol[j] = __ldg(&bias[tn + j]);
        lnsv[j] = __ldg(&lns[tn + j]);
        lnbv[j] = __ldg(&lnb[tn + j]);
    }
    float rsum[8], rsq[8];
#pragma unroll
    for (int i = 0; i < 8; i++) {
        int row = bm + tm + i;
        float4 r0 = __ldg((const float4*)(R + (size_t)row * 256 + tn));
        float4 r1 = __ldg((const float4*)(R + (size_t)row * 256 + tn + 4));
        float rr[8] = {r0.x, r0.y, r0.z, r0.w, r1.x, r1.y, r1.z, r1.w};
        float s1 = 0.f, s2 = 0.f;
#pragma unroll
        for (int j = 0; j < 8; j++) {
            float v = acc[i][j] + bcol[j] + rr[j];
            acc[i][j] = v;
            s1 += v;
            s2 += v * v;
        }
        rsum[i] = s1; rsq[i] = s2;
    }
#pragma unroll
    for (int d = 16; d > 0; d >>= 1) {
#pragma unroll
        for (int i = 0; i < 8; i++) {
            rsum[i] += __shfl_xor_sync(0xffffffffu, rsum[i], d);
            rsq[i]  += __shfl_xor_sync(0xffffffffu, rsq[i],  d);
        }
    }
#pragma unroll
    for (int i = 0; i < 8; i++) {
        int row = bm + tm + i;
        float mean = rsum[i] * (1.0f / 256.0f);
        float var  = rsq[i] * (1.0f / 256.0f) - mean * mean;
        float rs   = rsqrtf(var + 1e-6f);
        float o[8];
#pragma unroll
        for (int j = 0; j < 8; j++)
            o[j] = (acc[i][j] - mean) * rs * lnsv[j] + lnbv[j];
        *(float4*)(C + (size_t)row * 256 + tn)     = make_float4(o[0], o[1], o[2], o[3]);
        *(float4*)(C + (size_t)row * 256 + tn + 4) = make_float4(o[4], o[5], o[6], o[7]);
    }
}

// ---------------- K4: fused bilinear-gather + attention ----------------------
__global__ void __launch_bounds__(128) attn_kernel() {
    int p    = blockIdx.x;
    int t    = threadIdx.x;     // 128 threads: warp = head
    int a    = t >> 5;
    int lane = t & 31;
    int n  = p >> 12;
    int yy = (p >> 6) & 63;
    int xx = p & 63;

    __shared__ float s_off[32];
    __shared__ int   s_idx[SS][4];
    __shared__ float s_w[SS][4];

    if (t < 32) s_off[t] = g_off[p * 32 + t];
    __syncthreads();
    if (t < SS) {
        float oy = s_off[2 * t], ox = s_off[2 * t + 1];
        float yl = fminf(fmaxf((float)yy + oy, 0.f), 63.f);
        float xl = fminf(fmaxf((float)xx + ox, 0.f), 63.f);
        float y0f = floorf(yl), x0f = floorf(xl);
        int y0 = (int)y0f, x0 = (int)x0f;
        int y1 = min(y0 + 1, 63), x1 = min(x0 + 1, 63);
        float wy = yl - y0f, wx = xl - x0f;
        int base = n * (HH * WW * DD);
        s_idx[t][0] = base + (y0 * WW + x0) * DD;
        s_idx[t][1] = base + (y0 * WW + x1) * DD;
        s_idx[t][2] = base + (y1 * WW + x0) * DD;
        s_idx[t][3] = base + (y1 * WW + x1) * DD;
        s_w[t][0] = (1.f - wy) * (1.f - wx);
        s_w[t][1] = (1.f - wy) * wx;
        s_w[t][2] = wy * (1.f - wx);
        s_w[t][3] = wy * wx;
    }
    __syncthreads();

    int e0 = a * 64 + lane;
    int e1 = e0 + 32;
    float q0 = __ldg(&g_q[p * DD + e0]);
    float q1 = __ldg(&g_q[p * DD + e1]);

    float wck00 = __ldg(&g_Wck[e0]),      wck01 = __ldg(&g_Wck[e1]);
    float wck10 = __ldg(&g_Wck[DD + e0]), wck11 = __ldg(&g_Wck[DD + e1]);
    float bck0  = __ldg(&g_bck[e0]),      bck1  = __ldg(&g_bck[e1]);

    float sc[SS];
    float mx = -1e30f;
#pragma unroll
    for (int s = 0; s < SS; s++) {
        float oy = s_off[2 * s], ox = s_off[2 * s + 1];
        int   i0 = s_idx[s][0], i1 = s_idx[s][1], i2 = s_idx[s][2], i3 = s_idx[s][3];
        float w0 = s_w[s][0],  w1 = s_w[s][1],  w2 = s_w[s][2],  w3 = s_w[s][3];
        float k0 = w0 * __ldg(&g_ek[i0 + e0]) + w1 * __ldg(&g_ek[i1 + e0])
                 + w2 * __ldg(&g_ek[i2 + e0]) + w3 * __ldg(&g_ek[i3 + e0])
                 + oy * wck00 + ox * wck10 + bck0;
        float k1 = w0 * __ldg(&g_ek[i0 + e1]) + w1 * __ldg(&g_ek[i1 + e1])
                 + w2 * __ldg(&g_ek[i2 + e1]) + w3 * __ldg(&g_ek[i3 + e1])
                 + oy * wck01 + ox * wck11 + bck1;
        float part = q0 * k0 + q1 * k1;
#pragma unroll
        for (int d = 16; d > 0; d >>= 1)
            part += __shfl_xor_sync(0xffffffffu, part, d);
        sc[s] = part * 0.125f;   // / sqrt(64)
        mx = fmaxf(mx, sc[s]);
    }
    float denom = 0.f;
#pragma unroll
    for (int s = 0; s < SS; s++) { sc[s] = expf(sc[s] - mx); denom += sc[s]; }
    float inv = 1.0f / denom;

    float wcv00 = __ldg(&g_Wcv[e0]),      wcv01 = __ldg(&g_Wcv[e1]);
    float wcv10 = __ldg(&g_Wcv[DD + e0]), wcv11 = __ldg(&g_Wcv[DD + e1]);
    float bcv0  = __ldg(&g_bcv[e0]),      bcv1  = __ldg(&g_bcv[e1]);

    float acc0 = 0.f, acc1 = 0.f;
#pragma unroll
    for (int s = 0; s < SS; s++) {
        float oy = s_off[2 * s], ox = s_off[2 * s + 1];
        int   i0 = s_idx[s][0], i1 = s_idx[s][1], i2 = s_idx[s][2], i3 = s_idx[s][3];
        float w0 = s_w[s][0],  w1 = s_w[s][1],  w2 = s_w[s][2],  w3 = s_w[s][3];
        float v0 = w0 * __ldg(&g_ev[i0 + e0]) + w1 * __ldg(&g_ev[i1 + e0])
                 + w2 * __ldg(&g_ev[i2 + e0]) + w3 * __ldg(&g_ev[i3 + e0])
                 + oy * wcv00 + ox * wcv10 + bcv0;
        float v1 = w0 * __ldg(&g_ev[i0 + e1]) + w1 * __ldg(&g_ev[i1 + e1])
                 + w2 * __ldg(&g_ev[i2 + e1]) + w3 * __ldg(&g_ev[i3 + e1])
                 + oy * wcv01 + ox * wcv11 + bcv1;
        float ps = sc[s] * inv;
        acc0 += ps * v0;
        acc1 += ps * v1;
    }
    g_attn[p * DD + e0] = acc0;
    g_attn[p * DD + e1] = acc1;
}

// ---------------- launch ------------------------------------------------------
extern "C" void kernel_launch(void* const* d_in, const int* in_sizes, int n_in,
                              void* d_out, int out_size) {
    const float* hs    = (const float*)d_in[0];
    const float* ehs   = (const float*)d_in[1];
    const float* W_off = (const float*)d_in[2];
    const float* b_off = (const float*)d_in[3];
    const float* W_kvp = (const float*)d_in[4];
    const float* b_kvp = (const float*)d_in[5];
    const float* Wq    = (const float*)d_in[6];
    const float* bq    = (const float*)d_in[7];
    const float* Wk    = (const float*)d_in[8];
    const float* bk    = (const float*)d_in[9];
    const float* Wv    = (const float*)d_in[10];
    const float* bv    = (const float*)d_in[11];
    const float* Wo    = (const float*)d_in[12];
    const float* bo    = (const float*)d_in[13];
    const float *ln1_s, *ln1_b, *ln2_s, *ln2_b, *W1, *b1, *W2, *b2;
    if (n_in > 16 && in_sizes[16] == DD * MLPH) {
        // reference-signature order: ..., ln1_s, ln1_b, W1, b1, W2, b2, ln2_s, ln2_b
        ln1_s = (const float*)d_in[14]; ln1_b = (const float*)d_in[15];
        W1    = (const float*)d_in[16]; b1    = (const float*)d_in[17];
        W2    = (const float*)d_in[18]; b2    = (const float*)d_in[19];
        ln2_s = (const float*)d_in[20]; ln2_b = (const float*)d_in[21];
    } else {
        // setup_inputs dict order: ..., ln1_s, ln1_b, ln2_s, ln2_b, W1, b1, W2, b2
        ln1_s = (const float*)d_in[14]; ln1_b = (const float*)d_in[15];
        ln2_s = (const float*)d_in[16]; ln2_b = (const float*)d_in[17];
        W1    = (const float*)d_in[18]; b1    = (const float*)d_in[19];
        W2    = (const float*)d_in[20]; b2    = (const float*)d_in[21];
    }
    float* out = (float*)d_out;

    float *p_ek, *p_ev, *p_q, *p_attn, *p_x, *p_h;
    cudaGetSymbolAddress((void**)&p_ek,   g_ek);
    cudaGetSymbolAddress((void**)&p_ev,   g_ev);
    cudaGetSymbolAddress((void**)&p_q,    g_q);
    cudaGetSymbolAddress((void**)&p_attn, g_attn);
    cudaGetSymbolAddress((void**)&p_x,    g_x);
    cudaGetSymbolAddress((void**)&p_h,    g_h);

    dim3 blk(256);

    precompute_kernel<<<1, 256>>>(W_kvp, b_kvp, Wk, bk, Wv, bv);
    off_kernel<<<PP, 256>>>(hs, W_off, b_off);

    // ek = e @ Wk ; ev = e @ Wv ; q = hs @ Wq + bq  (batched, one launch)
    qkv_kernel<<<dim3(DD / 128, PP / 128, 3), blk>>>(ehs, hs, Wk, Wv, Wq, bq,
                                                     p_ek, p_ev, p_q);

    attn_kernel<<<PP, 128>>>();

    // x = LN1(attn @ Wo + bo + hs)   (fused)
    ln_gemm_kernel<<<PP / 64, blk>>>(p_attn, Wo, bo, hs, ln1_s, ln1_b, p_x, DD);

    // h = gelu(x @ W1 + b1)
    gemm_kernel<1><<<dim3(MLPH / 128, PP / 128), blk>>>(p_x, W1, b1, p_h, MLPH, DD);

    // out = LN2(h @ W2 + b2 + x)     (fused)
    ln_gemm_kernel<<<PP / 64, blk>>>(p_h, W2, b2, p_x, ln2_s, ln2_b, out, MLPH);
}

// round 16
// speedup vs baseline: 1.2373x; 1.2373x over previous
#include <cuda_runtime.h>
#include <math.h>
#include <mma.h>
using namespace nvcuda;

// Problem dims
#define PP   8192      // N*H*W
#define DD   256
#define SS   16
#define HH   64
#define WW   64
#define MLPH 1024

// ---------------- scratch (device globals; no runtime allocation) ----------
__device__ float g_off [PP * 32];        // [P, S, 2] scaled offsets
__device__ float g_ek  [PP * DD];        // e @ Wk
__device__ float g_ev  [PP * DD];        // e @ Wv
__device__ float g_q   [PP * DD];        // hs @ Wq + bq
__device__ float g_attn[PP * DD];        // attention output (pre-Wo)
__device__ float g_y1  [PP * DD];        // attn@Wo + bo + hs (pre-LN1)
__device__ float g_x   [PP * DD];        // after LN1
__device__ float g_h   [PP * MLPH];      // gelu(x@W1+b1)
__device__ float g_y2  [PP * DD];        // h@W2 + b2 + x (pre-LN2)
__device__ float g_Wck [2 * DD];         // W_kvp @ Wk
__device__ float g_Wcv [2 * DD];         // W_kvp @ Wv
__device__ float g_bck [DD];             // b_kvp @ Wk + bk
__device__ float g_bcv [DD];             // b_kvp @ Wv + bv

// ---------------- small helpers --------------------------------------------
__device__ __forceinline__ float gelu_f(float x) {
    // JAX gelu approximate=True (tanh form)
    float x3 = x * x * x;
    return 0.5f * x * (1.0f + tanhf(0.7978845608028654f * (x + 0.044715f * x3)));
}

// ---------------- K0: fold W_kvp/b_kvp through Wk/Wv ------------------------
__global__ void precompute_kernel(const float* __restrict__ W_kvp,
                                  const float* __restrict__ b_kvp,
                                  const float* __restrict__ Wk,
                                  const float* __restrict__ bk,
                                  const float* __restrict__ Wv,
                                  const float* __restrict__ bv) {
    int e = threadIdx.x;  // 0..255 output column (a*64+hd)
    float wk0 = 0.f, wk1 = 0.f, wv0 = 0.f, wv1 = 0.f, bkk = 0.f, bvv = 0.f;
    for (int d = 0; d < DD; d++) {
        float wkd = Wk[d * DD + e];
        float wvd = Wv[d * DD + e];
        float k0w = W_kvp[d];         // W_kvp[0][d]
        float k1w = W_kvp[DD + d];    // W_kvp[1][d]
        float bkv = b_kvp[d];
        wk0 += k0w * wkd; wk1 += k1w * wkd;
        wv0 += k0w * wvd; wv1 += k1w * wvd;
        bkk += bkv * wkd; bvv += bkv * wvd;
    }
    g_Wck[e] = wk0; g_Wck[DD + e] = wk1;
    g_Wcv[e] = wv0; g_Wcv[DD + e] = wv1;
    g_bck[e] = bkk + bk[e];
    g_bcv[e] = bvv + bv[e];
}

// ---------------- K1: offset predictor --------------------------------------
__global__ void off_kernel(const float* __restrict__ hs,
                           const float* __restrict__ W_off,
                           const float* __restrict__ b_off) {
    int p = blockIdx.x;
    int t = threadIdx.x;            // 256 threads
    __shared__ float s_hs[DD];
    __shared__ float s_part[8][32];
    s_hs[t] = hs[p * DD + t];
    __syncthreads();
    int o = t & 31;                 // output index s*2+k, 0..31
    int g = t >> 5;                 // 8 d-groups of 32
    float acc = 0.f;
#pragma unroll
    for (int j = 0; j < 32; j++) {
        int d = g * 32 + j;
        acc += s_hs[d] * W_off[d * 32 + o];   // coalesced: lanes -> consecutive o
    }
    s_part[g][o] = acc;
    __syncthreads();
    if (t < 32) {
        float s = 0.f;
#pragma unroll
        for (int gg = 0; gg < 8; gg++) s += s_part[gg][t];
        s += b_off[t];
        float sig = 1.0f / (1.0f + expf(-s));
        g_off[p * 32 + t] = 60.0f * sig - 30.0f;   // 2*30*sigmoid - 30
    }
}

// ---------------- tf32 WMMA 128x128x16 double-buffered GEMM body -------------
// C = A[M,K] @ B[K,N] (+bias) (+gelu | +residual R). 256 thr = 8 warps (4m x 2n),
// warp computes 32x64 via 2x4 m16n16k8 fragments. fp32 accumulate.
template <int EPI>  // 0: bias-only, 1: bias+gelu, 2: bias+residual
__device__ __forceinline__ void gemm_tf32_body(
        const float* __restrict__ A, const float* __restrict__ B,
        const float* __restrict__ bias, const float* __restrict__ R,
        float* __restrict__ C, int N, int K, int bm, int bn) {
    __shared__ float As[2][128][16];
    __shared__ float Bs[2][16][136];     // +8 pad
    __shared__ float patch[8][16][20];   // per-warp epilogue staging (ld=20, mult of 4)

    int t    = threadIdx.x;
    int wid  = t >> 5;
    int lane = t & 31;
    int wm = (wid & 3) * 32;             // warp row offset: 0,32,64,96
    int wn = (wid >> 2) * 64;            // warp col offset: 0,64

    // loaders: A 128x16 (2 float4/thread), B 16x128 (2 float4/thread)
    int ar = t >> 1,  ak = (t & 1) * 8;
    int br = t >> 4,  bc = (t & 15) * 8;
    const float* Ap = A + (size_t)(bm + ar) * K + ak;
    const float* Bp = B + (size_t)br * N + bn + bc;

    wmma::fragment<wmma::accumulator, 16, 16, 8, float> cf[2][4];
#pragma unroll
    for (int i = 0; i < 2; i++)
#pragma unroll
        for (int j = 0; j < 4; j++) wmma::fill_fragment(cf[i][j], 0.f);

    {   // prologue: stage 0
        float4 a0 = *(const float4*)Ap,  a1 = *(const float4*)(Ap + 4);
        float4 b0 = *(const float4*)Bp,  b1 = *(const float4*)(Bp + 4);
        *(float4*)&As[0][ar][ak]     = a0; *(float4*)&As[0][ar][ak + 4] = a1;
        *(float4*)&Bs[0][br][bc]     = b0; *(float4*)&Bs[0][br][bc + 4] = b1;
    }
    __syncthreads();

    int nk = K / 16;
    for (int ks = 0; ks < nk; ks++) {
        int cur = ks & 1;
        float4 a0, a1, b0, b1;
        if (ks + 1 < nk) {
            int k0 = (ks + 1) * 16;
            a0 = *(const float4*)(Ap + k0);
            a1 = *(const float4*)(Ap + k0 + 4);
            b0 = *(const float4*)(Bp + (size_t)k0 * N);
            b1 = *(const float4*)(Bp + (size_t)k0 * N + 4);
        }
#pragma unroll
        for (int kk = 0; kk < 2; kk++) {   // two k=8 subtiles
            wmma::fragment<wmma::matrix_a, 16, 16, 8, wmma::precision::tf32, wmma::row_major> af[2];
            wmma::fragment<wmma::matrix_b, 16, 16, 8, wmma::precision::tf32, wmma::row_major> bf[4];
#pragma unroll
            for (int i = 0; i < 2; i++) {
                wmma::load_matrix_sync(af[i], &As[cur][wm + i * 16][kk * 8], 16);
#pragma unroll
                for (int e = 0; e < af[i].num_elements; e++)
                    af[i].x[e] = wmma::__float_to_tf32(af[i].x[e]);
            }
#pragma unroll
            for (int j = 0; j < 4; j++) {
                wmma::load_matrix_sync(bf[j], &Bs[cur][kk * 8][wn + j * 16], 136);
#pragma unroll
                for (int e = 0; e < bf[j].num_elements; e++)
                    bf[j].x[e] = wmma::__float_to_tf32(bf[j].x[e]);
            }
#pragma unroll
            for (int i = 0; i < 2; i++)
#pragma unroll
                for (int j = 0; j < 4; j++)
                    wmma::mma_sync(cf[i][j], af[i], bf[j], cf[i][j]);
        }
        if (ks + 1 < nk) {
            int nxt = cur ^ 1;
            *(float4*)&As[nxt][ar][ak]     = a0; *(float4*)&As[nxt][ar][ak + 4] = a1;
            *(float4*)&Bs[nxt][br][bc]     = b0; *(float4*)&Bs[nxt][br][bc + 4] = b1;
            __syncthreads();
        }
    }

    // epilogue: per-warp fragment staging, then bias/gelu/residual + store
    int pr = lane >> 1;          // 0..15
    int pc = (lane & 1) * 8;     // 0 or 8
#pragma unroll
    for (int i = 0; i < 2; i++)
#pragma unroll
    for (int j = 0; j < 4; j++) {
        wmma::store_matrix_sync(&patch[wid][0][0], cf[i][j], 20, wmma::mem_row_major);
        __syncwarp();
        int grow = bm + wm + i * 16 + pr;
        int gcol = bn + wn + j * 16 + pc;
        float v[8];
#pragma unroll
        for (int e = 0; e < 8; e++) {
            v[e] = patch[wid][pr][pc + e];
            if (bias) v[e] += __ldg(&bias[gcol + e]);
            if (EPI == 1) v[e] = gelu_f(v[e]);
        }
        if (EPI == 2) {
            float4 r0 = __ldg((const float4*)(R + (size_t)grow * N + gcol));
            float4 r1 = __ldg((const float4*)(R + (size_t)grow * N + gcol + 4));
            v[0] += r0.x; v[1] += r0.y; v[2] += r0.z; v[3] += r0.w;
            v[4] += r1.x; v[5] += r1.y; v[6] += r1.z; v[7] += r1.w;
        }
        *(float4*)(C + (size_t)grow * N + gcol)     = make_float4(v[0], v[1], v[2], v[3]);
        *(float4*)(C + (size_t)grow * N + gcol + 4) = make_float4(v[4], v[5], v[6], v[7]);
        __syncwarp();
    }
}

template <int EPI>
__global__ void __launch_bounds__(256)
gemm_tf32_kernel(const float* __restrict__ A, const float* __restrict__ B,
                 const float* __restrict__ bias, const float* __restrict__ R,
                 float* __restrict__ C, int N, int K) {
    gemm_tf32_body<EPI>(A, B, bias, R, C, N, K, blockIdx.y * 128, blockIdx.x * 128);
}

// Batched K/V/Q projections in one launch (blockIdx.z selects the GEMM)
__global__ void __launch_bounds__(256)
qkv_kernel(const float* __restrict__ ehs, const float* __restrict__ hs,
           const float* __restrict__ Wk, const float* __restrict__ Wv,
           const float* __restrict__ Wq, const float* __restrict__ bq,
           float* __restrict__ ek, float* __restrict__ ev, float* __restrict__ q) {
    int bm = blockIdx.y * 128, bn = blockIdx.x * 128;
    if (blockIdx.z == 0)
        gemm_tf32_body<0>(ehs, Wk, nullptr, nullptr, ek, DD, DD, bm, bn);
    else if (blockIdx.z == 1)
        gemm_tf32_body<0>(ehs, Wv, nullptr, nullptr, ev, DD, DD, bm, bn);
    else
        gemm_tf32_body<0>(hs, Wq, bq, nullptr, q, DD, DD, bm, bn);
}

// ---------------- K4: fused bilinear-gather + attention ----------------------
__global__ void __launch_bounds__(128) attn_kernel() {
    int p    = blockIdx.x;
    int t    = threadIdx.x;     // 128 threads: warp = head
    int a    = t >> 5;
    int lane = t & 31;
    int n  = p >> 12;
    int yy = (p >> 6) & 63;
    int xx = p & 63;

    __shared__ float s_off[32];
    __shared__ int   s_idx[SS][4];
    __shared__ float s_w[SS][4];

    if (t < 32) s_off[t] = g_off[p * 32 + t];
    __syncthreads();
    if (t < SS) {
        float oy = s_off[2 * t], ox = s_off[2 * t + 1];
        float yl = fminf(fmaxf((float)yy + oy, 0.f), 63.f);
        float xl = fminf(fmaxf((float)xx + ox, 0.f), 63.f);
        float y0f = floorf(yl), x0f = floorf(xl);
        int y0 = (int)y0f, x0 = (int)x0f;
        int y1 = min(y0 + 1, 63), x1 = min(x0 + 1, 63);
        float wy = yl - y0f, wx = xl - x0f;
        int base = n * (HH * WW * DD);
        s_idx[t][0] = base + (y0 * WW + x0) * DD;
        s_idx[t][1] = base + (y0 * WW + x1) * DD;
        s_idx[t][2] = base + (y1 * WW + x0) * DD;
        s_idx[t][3] = base + (y1 * WW + x1) * DD;
        s_w[t][0] = (1.f - wy) * (1.f - wx);
        s_w[t][1] = (1.f - wy) * wx;
        s_w[t][2] = wy * (1.f - wx);
        s_w[t][3] = wy * wx;
    }
    __syncthreads();

    int e0 = a * 64 + lane;
    int e1 = e0 + 32;
    float q0 = __ldg(&g_q[p * DD + e0]);
    float q1 = __ldg(&g_q[p * DD + e1]);

    float wck00 = __ldg(&g_Wck[e0]),      wck01 = __ldg(&g_Wck[e1]);
    float wck10 = __ldg(&g_Wck[DD + e0]), wck11 = __ldg(&g_Wck[DD + e1]);
    float bck0  = __ldg(&g_bck[e0]),      bck1  = __ldg(&g_bck[e1]);

    float sc[SS];
    float mx = -1e30f;
#pragma unroll
    for (int s = 0; s < SS; s++) {
        float oy = s_off[2 * s], ox = s_off[2 * s + 1];
        int   i0 = s_idx[s][0], i1 = s_idx[s][1], i2 = s_idx[s][2], i3 = s_idx[s][3];
        float w0 = s_w[s][0],  w1 = s_w[s][1],  w2 = s_w[s][2],  w3 = s_w[s][3];
        float k0 = w0 * __ldg(&g_ek[i0 + e0]) + w1 * __ldg(&g_ek[i1 + e0])
                 + w2 * __ldg(&g_ek[i2 + e0]) + w3 * __ldg(&g_ek[i3 + e0])
                 + oy * wck00 + ox * wck10 + bck0;
        float k1 = w0 * __ldg(&g_ek[i0 + e1]) + w1 * __ldg(&g_ek[i1 + e1])
                 + w2 * __ldg(&g_ek[i2 + e1]) + w3 * __ldg(&g_ek[i3 + e1])
                 + oy * wck01 + ox * wck11 + bck1;
        float part = q0 * k0 + q1 * k1;
#pragma unroll
        for (int d = 16; d > 0; d >>= 1)
            part += __shfl_xor_sync(0xffffffffu, part, d);
        sc[s] = part * 0.125f;   // / sqrt(64)
        mx = fmaxf(mx, sc[s]);
    }
    float denom = 0.f;
#pragma unroll
    for (int s = 0; s < SS; s++) { sc[s] = expf(sc[s] - mx); denom += sc[s]; }
    float inv = 1.0f / denom;

    float wcv00 = __ldg(&g_Wcv[e0]),      wcv01 = __ldg(&g_Wcv[e1]);
    float wcv10 = __ldg(&g_Wcv[DD + e0]), wcv11 = __ldg(&g_Wcv[DD + e1]);
    float bcv0  = __ldg(&g_bcv[e0]),      bcv1  = __ldg(&g_bcv[e1]);

    float acc0 = 0.f, acc1 = 0.f;
#pragma unroll
    for (int s = 0; s < SS; s++) {
        float oy = s_off[2 * s], ox = s_off[2 * s + 1];
        int   i0 = s_idx[s][0], i1 = s_idx[s][1], i2 = s_idx[s][2], i3 = s_idx[s][3];
        float w0 = s_w[s][0],  w1 = s_w[s][1],  w2 = s_w[s][2],  w3 = s_w[s][3];
        float v0 = w0 * __ldg(&g_ev[i0 + e0]) + w1 * __ldg(&g_ev[i1 + e0])
                 + w2 * __ldg(&g_ev[i2 + e0]) + w3 * __ldg(&g_ev[i3 + e0])
                 + oy * wcv00 + ox * wcv10 + bcv0;
        float v1 = w0 * __ldg(&g_ev[i0 + e1]) + w1 * __ldg(&g_ev[i1 + e1])
                 + w2 * __ldg(&g_ev[i2 + e1]) + w3 * __ldg(&g_ev[i3 + e1])
                 + oy * wcv01 + ox * wcv11 + bcv1;
        float ps = sc[s] * inv;
        acc0 += ps * v0;
        acc1 += ps * v1;
    }
    g_attn[p * DD + e0] = acc0;
    g_attn[p * DD + e1] = acc1;
}

// ---------------- LayerNorm over D=256, float4, 64 threads/row ---------------
__global__ void __launch_bounds__(64)
ln_kernel(const float* __restrict__ in,
          const float* __restrict__ sc,
          const float* __restrict__ bi,
          float* __restrict__ out) {
    int p = blockIdx.x;
    int t = threadIdx.x;  // 0..63, each handles 4 consecutive elems
    float4 x4 = __ldg((const float4*)(in + p * DD + t * 4));
    float v1 = x4.x + x4.y + x4.z + x4.w;
    float v2 = x4.x * x4.x + x4.y * x4.y + x4.z * x4.z + x4.w * x4.w;
#pragma unroll
    for (int d = 16; d > 0; d >>= 1) {
        v1 += __shfl_xor_sync(0xffffffffu, v1, d);
        v2 += __shfl_xor_sync(0xffffffffu, v2, d);
    }
    __shared__ float s1[2], s2[2];
    if ((t & 31) == 0) { s1[t >> 5] = v1; s2[t >> 5] = v2; }
    __syncthreads();
    float sum = s1[0] + s1[1], sumsq = s2[0] + s2[1];
    float mean = sum * (1.0f / DD);
    float var  = sumsq * (1.0f / DD) - mean * mean;
    float rs = rsqrtf(var + 1e-6f);
    float4 sc4 = __ldg((const float4*)(sc + t * 4));
    float4 bi4 = __ldg((const float4*)(bi + t * 4));
    float4 o;
    o.x = (x4.x - mean) * rs * sc4.x + bi4.x;
    o.y = (x4.y - mean) * rs * sc4.y + bi4.y;
    o.z = (x4.z - mean) * rs * sc4.z + bi4.z;
    o.w = (x4.w - mean) * rs * sc4.w + bi4.w;
    *(float4*)(out + p * DD + t * 4) = o;
}

// ---------------- launch ------------------------------------------------------
extern "C" void kernel_launch(void* const* d_in, const int* in_sizes, int n_in,
                              void* d_out, int out_size) {
    const float* hs    = (const float*)d_in[0];
    const float* ehs   = (const float*)d_in[1];
    const float* W_off = (const float*)d_in[2];
    const float* b_off = (const float*)d_in[3];
    const float* W_kvp = (const float*)d_in[4];
    const float* b_kvp = (const float*)d_in[5];
    const float* Wq    = (const float*)d_in[6];
    const float* bq    = (const float*)d_in[7];
    const float* Wk    = (const float*)d_in[8];
    const float* bk    = (const float*)d_in[9];
    const float* Wv    = (const float*)d_in[10];
    const float* bv    = (const float*)d_in[11];
    const float* Wo    = (const float*)d_in[12];
    const float* bo    = (const float*)d_in[13];
    const float *ln1_s, *ln1_b, *ln2_s, *ln2_b, *W1, *b1, *W2, *b2;
    if (n_in > 16 && in_sizes[16] == DD * MLPH) {
        // reference-signature order: ..., ln1_s, ln1_b, W1, b1, W2, b2, ln2_s, ln2_b
        ln1_s = (const float*)d_in[14]; ln1_b = (const float*)d_in[15];
        W1    = (const float*)d_in[16]; b1    = (const float*)d_in[17];
        W2    = (const float*)d_in[18]; b2    = (const float*)d_in[19];
        ln2_s = (const float*)d_in[20]; ln2_b = (const float*)d_in[21];
    } else {
        // setup_inputs dict order: ..., ln1_s, ln1_b, ln2_s, ln2_b, W1, b1, W2, b2
        ln1_s = (const float*)d_in[14]; ln1_b = (const float*)d_in[15];
        ln2_s = (const float*)d_in[16]; ln2_b = (const float*)d_in[17];
        W1    = (const float*)d_in[18]; b1    = (const float*)d_in[19];
        W2    = (const float*)d_in[20]; b2    = (const float*)d_in[21];
    }
    float* out = (float*)d_out;

    float *p_ek, *p_ev, *p_q, *p_attn, *p_y1, *p_x, *p_h, *p_y2;
    cudaGetSymbolAddress((void**)&p_ek,   g_ek);
    cudaGetSymbolAddress((void**)&p_ev,   g_ev);
    cudaGetSymbolAddress((void**)&p_q,    g_q);
    cudaGetSymbolAddress((void**)&p_attn, g_attn);
    cudaGetSymbolAddress((void**)&p_y1,   g_y1);
    cudaGetSymbolAddress((void**)&p_x,    g_x);
    cudaGetSymbolAddress((void**)&p_h,    g_h);
    cudaGetSymbolAddress((void**)&p_y2,   g_y2);

    dim3 blk(256);

    precompute_kernel<<<1, 256>>>(W_kvp, b_kvp, Wk, bk, Wv, bv);
    off_kernel<<<PP, 256>>>(hs, W_off, b_off);

    // ek = e @ Wk ; ev = e @ Wv ; q = hs @ Wq + bq  (batched tf32, one launch)
    qkv_kernel<<<dim3(DD / 128, PP / 128, 3), blk>>>(ehs, hs, Wk, Wv, Wq, bq,
                                                     p_ek, p_ev, p_q);

    attn_kernel<<<PP, 128>>>();

    // y1 = attn @ Wo + bo + hs ; x = LN1(y1)
    gemm_tf32_kernel<2><<<dim3(DD / 128, PP / 128), blk>>>(p_attn, Wo, bo, hs, p_y1, DD, DD);
    ln_kernel<<<PP, 64>>>(p_y1, ln1_s, ln1_b, p_x);

    // h = gelu(x @ W1 + b1) ; y2 = h @ W2 + b2 + x ; out = LN2(y2)
    gemm_tf32_kernel<1><<<dim3(MLPH / 128, PP / 128), blk>>>(p_x, W1, b1, nullptr, p_h, MLPH, DD);
    gemm_tf32_kernel<2><<<dim3(DD / 128, PP / 128), blk>>>(p_h, W2, b2, p_x, p_y2, DD, MLPH);
    ln_kernel<<<PP, 64>>>(p_y2, ln2_s, ln2_b, out);
}

// round 17
// speedup vs baseline: 1.2575x; 1.0163x over previous
#include <cuda_runtime.h>
#include <math.h>
#include <mma.h>
using namespace nvcuda;

// Problem dims
#define PP   8192      // N*H*W
#define DD   256
#define SS   16
#define HH   64
#define WW   64
#define MLPH 1024

// ---------------- scratch (device globals; no runtime allocation) ----------
__device__ float g_off [PP * 32];        // [P, S, 2] scaled offsets
__device__ float g_ek  [PP * DD];        // e @ Wk
__device__ float g_ev  [PP * DD];        // e @ Wv
__device__ float g_q   [PP * DD];        // hs @ Wq + bq
__device__ float g_attn[PP * DD];        // attention output (pre-Wo)
__device__ float g_y1  [PP * DD];        // attn@Wo + bo + hs (pre-LN1)
__device__ float g_x   [PP * DD];        // after LN1
__device__ float g_h   [PP * MLPH];      // gelu(x@W1+b1)
__device__ float g_y2  [PP * DD];        // h@W2 + b2 + x (pre-LN2)
__device__ float g_Wck [2 * DD];         // W_kvp @ Wk
__device__ float g_Wcv [2 * DD];         // W_kvp @ Wv
__device__ float g_bck [DD];             // b_kvp @ Wk + bk
__device__ float g_bcv [DD];             // b_kvp @ Wv + bv

// ---------------- small helpers --------------------------------------------
__device__ __forceinline__ float gelu_f(float x) {
    // JAX gelu approximate=True (tanh form)
    float x3 = x * x * x;
    return 0.5f * x * (1.0f + tanhf(0.7978845608028654f * (x + 0.044715f * x3)));
}

__device__ __forceinline__ float to_tf32(float x) {
    float r;
    asm("cvt.rna.tf32.f32 %0, %1;" : "=f"(r) : "f"(x));
    return r;
}
__device__ __forceinline__ float4 to_tf32_4(float4 v) {
    v.x = to_tf32(v.x); v.y = to_tf32(v.y);
    v.z = to_tf32(v.z); v.w = to_tf32(v.w);
    return v;
}

// ---------------- K0: fold W_kvp/b_kvp through Wk/Wv ------------------------
__global__ void precompute_kernel(const float* __restrict__ W_kvp,
                                  const float* __restrict__ b_kvp,
                                  const float* __restrict__ Wk,
                                  const float* __restrict__ bk,
                                  const float* __restrict__ Wv,
                                  const float* __restrict__ bv) {
    int e = threadIdx.x;  // 0..255 output column (a*64+hd)
    float wk0 = 0.f, wk1 = 0.f, wv0 = 0.f, wv1 = 0.f, bkk = 0.f, bvv = 0.f;
    for (int d = 0; d < DD; d++) {
        float wkd = Wk[d * DD + e];
        float wvd = Wv[d * DD + e];
        float k0w = W_kvp[d];         // W_kvp[0][d]
        float k1w = W_kvp[DD + d];    // W_kvp[1][d]
        float bkv = b_kvp[d];
        wk0 += k0w * wkd; wk1 += k1w * wkd;
        wv0 += k0w * wvd; wv1 += k1w * wvd;
        bkk += bkv * wkd; bvv += bkv * wvd;
    }
    g_Wck[e] = wk0; g_Wck[DD + e] = wk1;
    g_Wcv[e] = wv0; g_Wcv[DD + e] = wv1;
    g_bck[e] = bkk + bk[e];
    g_bcv[e] = bvv + bv[e];
}

// ---------------- K1: offset predictor --------------------------------------
__global__ void off_kernel(const float* __restrict__ hs,
                           const float* __restrict__ W_off,
                           const float* __restrict__ b_off) {
    int p = blockIdx.x;
    int t = threadIdx.x;            // 256 threads
    __shared__ float s_hs[DD];
    __shared__ float s_part[8][32];
    s_hs[t] = hs[p * DD + t];
    __syncthreads();
    int o = t & 31;                 // output index s*2+k, 0..31
    int g = t >> 5;                 // 8 d-groups of 32
    float acc = 0.f;
#pragma unroll
    for (int j = 0; j < 32; j++) {
        int d = g * 32 + j;
        acc += s_hs[d] * W_off[d * 32 + o];   // coalesced: lanes -> consecutive o
    }
    s_part[g][o] = acc;
    __syncthreads();
    if (t < 32) {
        float s = 0.f;
#pragma unroll
        for (int gg = 0; gg < 8; gg++) s += s_part[gg][t];
        s += b_off[t];
        float sig = 1.0f / (1.0f + expf(-s));
        g_off[p * 32 + t] = 60.0f * sig - 30.0f;   // 2*30*sigmoid - 30
    }
}

// ---------------- tf32 WMMA 128x128x16 double-buffered GEMM body -------------
// C = A[M,K] @ B[K,N] (+bias) (+gelu | +residual R). 256 thr = 8 warps (4m x 2n),
// warp computes 32x64 via 2x4 m16n16k8 fragments. fp32 accumulate.
// Values are truncated to tf32 ONCE at smem-store time; fragment loads feed
// mma_sync directly (cvt.rna idempotent -> numerics identical to per-frag cvt).
template <int EPI>  // 0: bias-only, 1: bias+gelu, 2: bias+residual
__device__ __forceinline__ void gemm_tf32_body(
        const float* __restrict__ A, const float* __restrict__ B,
        const float* __restrict__ bias, const float* __restrict__ R,
        float* __restrict__ C, int N, int K, int bm, int bn) {
    __shared__ float As[2][128][20];     // padded: stride 20 floats (bank-safe)
    __shared__ float Bs[2][16][136];     // +8 pad
    __shared__ float patch[8][16][20];   // per-warp epilogue staging

    int t    = threadIdx.x;
    int wid  = t >> 5;
    int lane = t & 31;
    int wm = (wid & 3) * 32;             // warp row offset: 0,32,64,96
    int wn = (wid >> 2) * 64;            // warp col offset: 0,64

    // loaders: A 128x16 (2 float4/thread), B 16x128 (2 float4/thread)
    int ar = t >> 1,  ak = (t & 1) * 8;
    int br = t >> 4,  bc = (t & 15) * 8;
    const float* Ap = A + (size_t)(bm + ar) * K + ak;
    const float* Bp = B + (size_t)br * N + bn + bc;

    wmma::fragment<wmma::accumulator, 16, 16, 8, float> cf[2][4];
#pragma unroll
    for (int i = 0; i < 2; i++)
#pragma unroll
        for (int j = 0; j < 4; j++) wmma::fill_fragment(cf[i][j], 0.f);

    {   // prologue: stage 0 (truncate at store)
        float4 a0 = to_tf32_4(*(const float4*)Ap);
        float4 a1 = to_tf32_4(*(const float4*)(Ap + 4));
        float4 b0 = to_tf32_4(*(const float4*)Bp);
        float4 b1 = to_tf32_4(*(const float4*)(Bp + 4));
        *(float4*)&As[0][ar][ak]     = a0; *(float4*)&As[0][ar][ak + 4] = a1;
        *(float4*)&Bs[0][br][bc]     = b0; *(float4*)&Bs[0][br][bc + 4] = b1;
    }
    __syncthreads();

    int nk = K / 16;
    for (int ks = 0; ks < nk; ks++) {
        int cur = ks & 1;
        float4 a0, a1, b0, b1;
        if (ks + 1 < nk) {
            int k0 = (ks + 1) * 16;
            a0 = *(const float4*)(Ap + k0);
            a1 = *(const float4*)(Ap + k0 + 4);
            b0 = *(const float4*)(Bp + (size_t)k0 * N);
            b1 = *(const float4*)(Bp + (size_t)k0 * N + 4);
        }
#pragma unroll
        for (int kk = 0; kk < 2; kk++) {   // two k=8 subtiles
            wmma::fragment<wmma::matrix_a, 16, 16, 8, wmma::precision::tf32, wmma::row_major> af[2];
            wmma::fragment<wmma::matrix_b, 16, 16, 8, wmma::precision::tf32, wmma::row_major> bf[4];
#pragma unroll
            for (int i = 0; i < 2; i++)
                wmma::load_matrix_sync(af[i], &As[cur][wm + i * 16][kk * 8], 20);
#pragma unroll
            for (int j = 0; j < 4; j++)
                wmma::load_matrix_sync(bf[j], &Bs[cur][kk * 8][wn + j * 16], 136);
#pragma unroll
            for (int i = 0; i < 2; i++)
#pragma unroll
                for (int j = 0; j < 4; j++)
                    wmma::mma_sync(cf[i][j], af[i], bf[j], cf[i][j]);
        }
        if (ks + 1 < nk) {
            int nxt = cur ^ 1;
            *(float4*)&As[nxt][ar][ak]     = to_tf32_4(a0);
            *(float4*)&As[nxt][ar][ak + 4] = to_tf32_4(a1);
            *(float4*)&Bs[nxt][br][bc]     = to_tf32_4(b0);
            *(float4*)&Bs[nxt][br][bc + 4] = to_tf32_4(b1);
            __syncthreads();
        }
    }

    // epilogue: per-warp fragment staging, then bias/gelu/residual + store
    int pr = lane >> 1;          // 0..15
    int pc = (lane & 1) * 8;     // 0 or 8
#pragma unroll
    for (int i = 0; i < 2; i++)
#pragma unroll
    for (int j = 0; j < 4; j++) {
        wmma::store_matrix_sync(&patch[wid][0][0], cf[i][j], 20, wmma::mem_row_major);
        __syncwarp();
        int grow = bm + wm + i * 16 + pr;
        int gcol = bn + wn + j * 16 + pc;
        float v[8];
#pragma unroll
        for (int e = 0; e < 8; e++) {
            v[e] = patch[wid][pr][pc + e];
            if (bias) v[e] += __ldg(&bias[gcol + e]);
            if (EPI == 1) v[e] = gelu_f(v[e]);
        }
        if (EPI == 2) {
            float4 r0 = __ldg((const float4*)(R + (size_t)grow * N + gcol));
            float4 r1 = __ldg((const float4*)(R + (size_t)grow * N + gcol + 4));
            v[0] += r0.x; v[1] += r0.y; v[2] += r0.z; v[3] += r0.w;
            v[4] += r1.x; v[5] += r1.y; v[6] += r1.z; v[7] += r1.w;
        }
        *(float4*)(C + (size_t)grow * N + gcol)     = make_float4(v[0], v[1], v[2], v[3]);
        *(float4*)(C + (size_t)grow * N + gcol + 4) = make_float4(v[4], v[5], v[6], v[7]);
        __syncwarp();
    }
}

template <int EPI>
__global__ void __launch_bounds__(256)
gemm_tf32_kernel(const float* __restrict__ A, const float* __restrict__ B,
                 const float* __restrict__ bias, const float* __restrict__ R,
                 float* __restrict__ C, int N, int K) {
    gemm_tf32_body<EPI>(A, B, bias, R, C, N, K, blockIdx.y * 128, blockIdx.x * 128);
}

// Batched K/V/Q projections in one launch (blockIdx.z selects the GEMM)
__global__ void __launch_bounds__(256)
qkv_kernel(const float* __restrict__ ehs, const float* __restrict__ hs,
           const float* __restrict__ Wk, const float* __restrict__ Wv,
           const float* __restrict__ Wq, const float* __restrict__ bq,
           float* __restrict__ ek, float* __restrict__ ev, float* __restrict__ q) {
    int bm = blockIdx.y * 128, bn = blockIdx.x * 128;
    if (blockIdx.z == 0)
        gemm_tf32_body<0>(ehs, Wk, nullptr, nullptr, ek, DD, DD, bm, bn);
    else if (blockIdx.z == 1)
        gemm_tf32_body<0>(ehs, Wv, nullptr, nullptr, ev, DD, DD, bm, bn);
    else
        gemm_tf32_body<0>(hs, Wq, bq, nullptr, q, DD, DD, bm, bn);
}

// ---------------- K4: fused bilinear-gather + attention ----------------------
__global__ void __launch_bounds__(128) attn_kernel() {
    int p    = blockIdx.x;
    int t    = threadIdx.x;     // 128 threads: warp = head
    int a    = t >> 5;
    int lane = t & 31;
    int n  = p >> 12;
    int yy = (p >> 6) & 63;
    int xx = p & 63;

    __shared__ float s_off[32];
    __shared__ int   s_idx[SS][4];
    __shared__ float s_w[SS][4];

    if (t < 32) s_off[t] = g_off[p * 32 + t];
    __syncthreads();
    if (t < SS) {
        float oy = s_off[2 * t], ox = s_off[2 * t + 1];
        float yl = fminf(fmaxf((float)yy + oy, 0.f), 63.f);
        float xl = fminf(fmaxf((float)xx + ox, 0.f), 63.f);
        float y0f = floorf(yl), x0f = floorf(xl);
        int y0 = (int)y0f, x0 = (int)x0f;
        int y1 = min(y0 + 1, 63), x1 = min(x0 + 1, 63);
        float wy = yl - y0f, wx = xl - x0f;
        int base = n * (HH * WW * DD);
        s_idx[t][0] = base + (y0 * WW + x0) * DD;
        s_idx[t][1] = base + (y0 * WW + x1) * DD;
        s_idx[t][2] = base + (y1 * WW + x0) * DD;
        s_idx[t][3] = base + (y1 * WW + x1) * DD;
        s_w[t][0] = (1.f - wy) * (1.f - wx);
        s_w[t][1] = (1.f - wy) * wx;
        s_w[t][2] = wy * (1.f - wx);
        s_w[t][3] = wy * wx;
    }
    __syncthreads();

    int e0 = a * 64 + lane;
    int e1 = e0 + 32;
    float q0 = __ldg(&g_q[p * DD + e0]);
    float q1 = __ldg(&g_q[p * DD + e1]);

    float wck00 = __ldg(&g_Wck[e0]),      wck01 = __ldg(&g_Wck[e1]);
    float wck10 = __ldg(&g_Wck[DD + e0]), wck11 = __ldg(&g_Wck[DD + e1]);
    float bck0  = __ldg(&g_bck[e0]),      bck1  = __ldg(&g_bck[e1]);

    float sc[SS];
    float mx = -1e30f;
#pragma unroll
    for (int s = 0; s < SS; s++) {
        float oy = s_off[2 * s], ox = s_off[2 * s + 1];
        int   i0 = s_idx[s][0], i1 = s_idx[s][1], i2 = s_idx[s][2], i3 = s_idx[s][3];
        float w0 = s_w[s][0],  w1 = s_w[s][1],  w2 = s_w[s][2],  w3 = s_w[s][3];
        float k0 = w0 * __ldg(&g_ek[i0 + e0]) + w1 * __ldg(&g_ek[i1 + e0])
                 + w2 * __ldg(&g_ek[i2 + e0]) + w3 * __ldg(&g_ek[i3 + e0])
                 + oy * wck00 + ox * wck10 + bck0;
        float k1 = w0 * __ldg(&g_ek[i0 + e1]) + w1 * __ldg(&g_ek[i1 + e1])
                 + w2 * __ldg(&g_ek[i2 + e1]) + w3 * __ldg(&g_ek[i3 + e1])
                 + oy * wck01 + ox * wck11 + bck1;
        float part = q0 * k0 + q1 * k1;
#pragma unroll
        for (int d = 16; d > 0; d >>= 1)
            part += __shfl_xor_sync(0xffffffffu, part, d);
        sc[s] = part * 0.125f;   // / sqrt(64)
        mx = fmaxf(mx, sc[s]);
    }
    float denom = 0.f;
#pragma unroll
    for (int s = 0; s < SS; s++) { sc[s] = expf(sc[s] - mx); denom += sc[s]; }
    float inv = 1.0f / denom;

    float wcv00 = __ldg(&g_Wcv[e0]),      wcv01 = __ldg(&g_Wcv[e1]);
    float wcv10 = __ldg(&g_Wcv[DD + e0]), wcv11 = __ldg(&g_Wcv[DD + e1]);
    float bcv0  = __ldg(&g_bcv[e0]),      bcv1  = __ldg(&g_bcv[e1]);

    float acc0 = 0.f, acc1 = 0.f;
#pragma unroll
    for (int s = 0; s < SS; s++) {
        float oy = s_off[2 * s], ox = s_off[2 * s + 1];
        int   i0 = s_idx[s][0], i1 = s_idx[s][1], i2 = s_idx[s][2], i3 = s_idx[s][3];
        float w0 = s_w[s][0],  w1 = s_w[s][1],  w2 = s_w[s][2],  w3 = s_w[s][3];
        float v0 = w0 * __ldg(&g_ev[i0 + e0]) + w1 * __ldg(&g_ev[i1 + e0])
                 + w2 * __ldg(&g_ev[i2 + e0]) + w3 * __ldg(&g_ev[i3 + e0])
                 + oy * wcv00 + ox * wcv10 + bcv0;
        float v1 = w0 * __ldg(&g_ev[i0 + e1]) + w1 * __ldg(&g_ev[i1 + e1])
                 + w2 * __ldg(&g_ev[i2 + e1]) + w3 * __ldg(&g_ev[i3 + e1])
                 + oy * wcv01 + ox * wcv11 + bcv1;
        float ps = sc[s] * inv;
        acc0 += ps * v0;
        acc1 += ps * v1;
    }
    g_attn[p * DD + e0] = acc0;
    g_attn[p * DD + e1] = acc1;
}

// ---------------- LayerNorm over D=256, float4, 64 threads/row ---------------
__global__ void __launch_bounds__(64)
ln_kernel(const float* __restrict__ in,
          const float* __restrict__ sc,
          const float* __restrict__ bi,
          float* __restrict__ out) {
    int p = blockIdx.x;
    int t = threadIdx.x;  // 0..63, each handles 4 consecutive elems
    float4 x4 = __ldg((const float4*)(in + p * DD + t * 4));
    float v1 = x4.x + x4.y + x4.z + x4.w;
    float v2 = x4.x * x4.x + x4.y * x4.y + x4.z * x4.z + x4.w * x4.w;
#pragma unroll
    for (int d = 16; d > 0; d >>= 1) {
        v1 += __shfl_xor_sync(0xffffffffu, v1, d);
        v2 += __shfl_xor_sync(0xffffffffu, v2, d);
    }
    __shared__ float s1[2], s2[2];
    if ((t & 31) == 0) { s1[t >> 5] = v1; s2[t >> 5] = v2; }
    __syncthreads();
    float sum = s1[0] + s1[1], sumsq = s2[0] + s2[1];
    float mean = sum * (1.0f / DD);
    float var  = sumsq * (1.0f / DD) - mean * mean;
    float rs = rsqrtf(var + 1e-6f);
    float4 sc4 = __ldg((const float4*)(sc + t * 4));
    float4 bi4 = __ldg((const float4*)(bi + t * 4));
    float4 o;
    o.x = (x4.x - mean) * rs * sc4.x + bi4.x;
    o.y = (x4.y - mean) * rs * sc4.y + bi4.y;
    o.z = (x4.z - mean) * rs * sc4.z + bi4.z;
    o.w = (x4.w - mean) * rs * sc4.w + bi4.w;
    *(float4*)(out + p * DD + t * 4) = o;
}

// ---------------- launch ------------------------------------------------------
extern "C" void kernel_launch(void* const* d_in, const int* in_sizes, int n_in,
                              void* d_out, int out_size) {
    const float* hs    = (const float*)d_in[0];
    const float* ehs   = (const float*)d_in[1];
    const float* W_off = (const float*)d_in[2];
    const float* b_off = (const float*)d_in[3];
    const float* W_kvp = (const float*)d_in[4];
    const float* b_kvp = (const float*)d_in[5];
    const float* Wq    = (const float*)d_in[6];
    const float* bq    = (const float*)d_in[7];
    const float* Wk    = (const float*)d_in[8];
    const float* bk    = (const float*)d_in[9];
    const float* Wv    = (const float*)d_in[10];
    const float* bv    = (const float*)d_in[11];
    const float* Wo    = (const float*)d_in[12];
    const float* bo    = (const float*)d_in[13];
    const float *ln1_s, *ln1_b, *ln2_s, *ln2_b, *W1, *b1, *W2, *b2;
    if (n_in > 16 && in_sizes[16] == DD * MLPH) {
        // reference-signature order: ..., ln1_s, ln1_b, W1, b1, W2, b2, ln2_s, ln2_b
        ln1_s = (const float*)d_in[14]; ln1_b = (const float*)d_in[15];
        W1    = (const float*)d_in[16]; b1    = (const float*)d_in[17];
        W2    = (const float*)d_in[18]; b2    = (const float*)d_in[19];
        ln2_s = (const float*)d_in[20]; ln2_b = (const float*)d_in[21];
    } else {
        // setup_inputs dict order: ..., ln1_s, ln1_b, ln2_s, ln2_b, W1, b1, W2, b2
        ln1_s = (const float*)d_in[14]; ln1_b = (const float*)d_in[15];
        ln2_s = (const float*)d_in[16]; ln2_b = (const float*)d_in[17];
        W1    = (const float*)d_in[18]; b1    = (const float*)d_in[19];
        W2    = (const float*)d_in[20]; b2    = (const float*)d_in[21];
    }
    float* out = (float*)d_out;

    float *p_ek, *p_ev, *p_q, *p_attn, *p_y1, *p_x, *p_h, *p_y2;
    cudaGetSymbolAddress((void**)&p_ek,   g_ek);
    cudaGetSymbolAddress((void**)&p_ev,   g_ev);
    cudaGetSymbolAddress((void**)&p_q,    g_q);
    cudaGetSymbolAddress((void**)&p_attn, g_attn);
    cudaGetSymbolAddress((void**)&p_y1,   g_y1);
    cudaGetSymbolAddress((void**)&p_x,    g_x);
    cudaGetSymbolAddress((void**)&p_h,    g_h);
    cudaGetSymbolAddress((void**)&p_y2,   g_y2);

    dim3 blk(256);

    precompute_kernel<<<1, 256>>>(W_kvp, b_kvp, Wk, bk, Wv, bv);
    off_kernel<<<PP, 256>>>(hs, W_off, b_off);

    // ek = e @ Wk ; ev = e @ Wv ; q = hs @ Wq + bq  (batched tf32, one launch)
    qkv_kernel<<<dim3(DD / 128, PP / 128, 3), blk>>>(ehs, hs, Wk, Wv, Wq, bq,
                                                     p_ek, p_ev, p_q);

    attn_kernel<<<PP, 128>>>();

    // y1 = attn @ Wo + bo + hs ; x = LN1(y1)
    gemm_tf32_kernel<2><<<dim3(DD / 128, PP / 128), blk>>>(p_attn, Wo, bo, hs, p_y1, DD, DD);
    ln_kernel<<<PP, 64>>>(p_y1, ln1_s, ln1_b, p_x);

    // h = gelu(x @ W1 + b1) ; y2 = h @ W2 + b2 + x ; out = LN2(y2)
    gemm_tf32_kernel<1><<<dim3(MLPH / 128, PP / 128), blk>>>(p_x, W1, b1, nullptr, p_h, MLPH, DD);
    gemm_tf32_kernel<2><<<dim3(DD / 128, PP / 128), blk>>>(p_h, W2, b2, p_x, p_y2, DD, MLPH);
    ln_kernel<<<PP, 64>>>(p_y2, ln2_s, ln2_b, out);
}